// round 8
// baseline (speedup 1.0000x reference)
#include <cuda_runtime.h>
#include <math.h>

#define B    16
#define IN   1024
#define HH   1024
#define DKK  1024
#define D1   4096
#define LRC  0.01f

// ---------------- scratch (allocation-free) ----------------
__device__ __align__(16) float g_K  [B * DKK];          // b-major
__device__ __align__(16) float g_V  [B * HH];           // b-major
__device__ __align__(16) float g_G  [B * D1];           // b-major
__device__ __align__(16) float g_Gp [B * D1];           // b-major
__device__ __align__(16) float g_Hd [B * HH];           // b-major
__device__ __align__(16) float g_dHt[HH * B];           // i-major
__device__ __align__(16) float g_dZt[D1 * B];           // j-major, pre-scaled by LR

__device__ __forceinline__ float warp_sum(float v) {
    v += __shfl_xor_sync(0xffffffffu, v, 16);
    v += __shfl_xor_sync(0xffffffffu, v, 8);
    v += __shfl_xor_sync(0xffffffffu, v, 4);
    v += __shfl_xor_sync(0xffffffffu, v, 2);
    v += __shfl_xor_sync(0xffffffffu, v, 1);
    return v;
}
__device__ __forceinline__ float dot4(float4 a, float4 b) {
    return a.x * b.x + a.y * b.y + a.z * b.z + a.w * b.w;
}

// ---------------- proj: rows 0..1023 -> K, 1024..2047 -> V ----------------
__global__ void proj_kernel(const float* __restrict__ X,
                            const float* __restrict__ Wk,
                            const float* __restrict__ Wv) {
    __shared__ float sm[4][2][64];
    int w = threadIdx.x >> 5, lane = threadIdx.x & 31;
    int rgl = w >> 1, half = w & 1;
    int rg = blockIdx.x * 4 + rgl;            // 0..511
    const float* Wb = (rg >> 8) ? Wv : Wk;
    int row0 = (rg * 4) & 1023;
    int ibase = half * 512;
    const float* wp = Wb + (size_t)row0 * IN + ibase;
    const float* xp = X + ibase;

    float acc[4][16];
#pragma unroll
    for (int r = 0; r < 4; r++)
#pragma unroll
        for (int b = 0; b < 16; b++) acc[r][b] = 0.f;

#pragma unroll
    for (int it = 0; it < 4; it++) {
        int i = it * 128 + lane * 4;
        float4 wv[4];
#pragma unroll
        for (int r = 0; r < 4; r++) wv[r] = __ldg((const float4*)(wp + r * IN + i));
#pragma unroll
        for (int b = 0; b < 16; b++) {
            float4 x4 = __ldg((const float4*)(xp + b * IN + i));
#pragma unroll
            for (int r = 0; r < 4; r++) acc[r][b] += dot4(wv[r], x4);
        }
    }
#pragma unroll
    for (int r = 0; r < 4; r++)
#pragma unroll
        for (int b = 0; b < 16; b++) acc[r][b] = warp_sum(acc[r][b]);
    if (lane == 0) {
#pragma unroll
        for (int r = 0; r < 4; r++)
#pragma unroll
            for (int b = 0; b < 16; b++) sm[rgl][half][r * 16 + b] = acc[r][b];
    }
    __syncthreads();
    {
        int t = threadIdx.x;
        int rg2 = t >> 6, r = (t >> 4) & 3, b = t & 15;
        float v = sm[rg2][0][r * 16 + b] + sm[rg2][1][r * 16 + b];
        int row = (blockIdx.x * 4 + rg2) * 4 + r;
        float* o = (row >> 10) ? g_V : g_K;
        o[b * 1024 + (row & 1023)] = v;
    }
}

// ---------------- zgelu: Z = K @ W0^T ; G, Gp ----------------
__global__ void zgelu_kernel(const float* __restrict__ W0) {
    __shared__ float sm[4][2][64];
    int w = threadIdx.x >> 5, lane = threadIdx.x & 31;
    int rgl = w >> 1, half = w & 1;
    int rg = blockIdx.x * 4 + rgl;            // 0..1023
    int j0 = rg * 4;
    int ibase = half * 512;
    const float* wp = W0 + (size_t)j0 * DKK + ibase;

    float acc[4][16];
#pragma unroll
    for (int r = 0; r < 4; r++)
#pragma unroll
        for (int b = 0; b < 16; b++) acc[r][b] = 0.f;

#pragma unroll
    for (int it = 0; it < 4; it++) {
        int i = it * 128 + lane * 4;
        float4 wv[4];
#pragma unroll
        for (int r = 0; r < 4; r++) wv[r] = __ldg((const float4*)(wp + r * DKK + i));
#pragma unroll
        for (int b = 0; b < 16; b++) {
            float4 k4 = *(const float4*)(g_K + b * DKK + ibase + i);
#pragma unroll
            for (int r = 0; r < 4; r++) acc[r][b] += dot4(wv[r], k4);
        }
    }
#pragma unroll
    for (int r = 0; r < 4; r++)
#pragma unroll
        for (int b = 0; b < 16; b++) acc[r][b] = warp_sum(acc[r][b]);
    if (lane == 0) {
#pragma unroll
        for (int r = 0; r < 4; r++)
#pragma unroll
            for (int b = 0; b < 16; b++) sm[rgl][half][r * 16 + b] = acc[r][b];
    }
    __syncthreads();
    {
        int t = threadIdx.x;
        int rg2 = t >> 6, r = (t >> 4) & 3, b = t & 15;
        float z = sm[rg2][0][r * 16 + b] + sm[rg2][1][r * 16 + b];
        int j = (blockIdx.x * 4 + rg2) * 4 + r;
        float c  = 0.5f * (1.f + erff(z * 0.70710678118654752f));
        float g  = z * c;
        float gp = c + z * 0.39894228040143268f * expf(-0.5f * z * z);
        g_G [b * D1 + j] = g;
        g_Gp[b * D1 + j] = gp;
    }
}

// ---------------- hdh: Hd = G @ W1^T ; dH ----------------
__global__ void hdh_kernel(const float* __restrict__ W1) {
    __shared__ float sm[2][4][64];
    int w = threadIdx.x >> 5, lane = threadIdx.x & 31;
    int rgl = w >> 2, s = w & 3;
    int rg = blockIdx.x * 2 + rgl;            // 0..255
    int i0 = rg * 4;
    int jbase = s * 1024;
    const float* wp = W1 + (size_t)i0 * D1 + jbase;

    float acc[4][16];
#pragma unroll
    for (int r = 0; r < 4; r++)
#pragma unroll
        for (int b = 0; b < 16; b++) acc[r][b] = 0.f;

#pragma unroll
    for (int it = 0; it < 8; it++) {
        int j = it * 128 + lane * 4;
        float4 wv[4];
#pragma unroll
        for (int r = 0; r < 4; r++) wv[r] = __ldg((const float4*)(wp + r * D1 + j));
#pragma unroll
        for (int b = 0; b < 16; b++) {
            float4 g4 = *(const float4*)(g_G + b * D1 + jbase + j);
#pragma unroll
            for (int r = 0; r < 4; r++) acc[r][b] += dot4(wv[r], g4);
        }
    }
#pragma unroll
    for (int r = 0; r < 4; r++)
#pragma unroll
        for (int b = 0; b < 16; b++) acc[r][b] = warp_sum(acc[r][b]);
    if (lane == 0) {
#pragma unroll
        for (int r = 0; r < 4; r++)
#pragma unroll
            for (int b = 0; b < 16; b++) sm[rgl][s][r * 16 + b] = acc[r][b];
    }
    __syncthreads();
    if (threadIdx.x < 128) {
        int t = threadIdx.x;
        int rg2 = t >> 6, r = (t >> 4) & 3, b = t & 15;
        float h = sm[rg2][0][r * 16 + b] + sm[rg2][1][r * 16 + b]
                + sm[rg2][2][r * 16 + b] + sm[rg2][3][r * 16 + b];
        int i = (blockIdx.x * 2 + rg2) * 4 + r;
        g_Hd [b * HH + i] = h;
        g_dHt[i * B + b]  = (h - g_V[b * HH + i]) * (1.0f / (float)HH);
    }
}

// ---------------- dZ direct (blocks 0..127) | output GEMV (blocks 128..383) ----------------
// dZ[b,j] = LR * Gp[b,j] * sum_i dH[b,i] * W1[i,j]; stored j-major g_dZt[j*16+b].
__global__ void dz_out_kernel(const float* __restrict__ W1,
                              const float* __restrict__ Wo,
                              float* __restrict__ out) {
    int tid = threadIdx.x;
    if (blockIdx.x < 128) {
        __shared__ float sred[8][32 * 16];      // [ic][j_l*16+b]
        int j_l = tid & 31;                     // 0..31
        int ic  = tid >> 5;                     // 0..7
        int j   = blockIdx.x * 32 + j_l;

        float acc[16];
#pragma unroll
        for (int b = 0; b < 16; b++) acc[b] = 0.f;

        const float* wp = W1 + (size_t)(ic * 128) * D1 + j;
        const float* dp = g_dHt + (ic * 128) * B;
#pragma unroll 4
        for (int r = 0; r < 128; r++) {
            float w = __ldg(wp + (size_t)r * D1);
            float4 d0 = *(const float4*)(dp + r * B);
            float4 d1 = *(const float4*)(dp + r * B + 4);
            float4 d2 = *(const float4*)(dp + r * B + 8);
            float4 d3 = *(const float4*)(dp + r * B + 12);
            acc[0]  += d0.x * w;  acc[1]  += d0.y * w;  acc[2]  += d0.z * w;  acc[3]  += d0.w * w;
            acc[4]  += d1.x * w;  acc[5]  += d1.y * w;  acc[6]  += d1.z * w;  acc[7]  += d1.w * w;
            acc[8]  += d2.x * w;  acc[9]  += d2.y * w;  acc[10] += d2.z * w;  acc[11] += d2.w * w;
            acc[12] += d3.x * w;  acc[13] += d3.y * w;  acc[14] += d3.z * w;  acc[15] += d3.w * w;
        }
#pragma unroll
        for (int b = 0; b < 16; b++) sred[ic][j_l * 16 + b] = acc[b];
        __syncthreads();
#pragma unroll
        for (int q = 0; q < 2; q++) {
            int idx = q * 256 + tid;            // j_l*16 + b
            int jj  = idx >> 4;
            int b   = idx & 15;
            float s = 0.f;
#pragma unroll
            for (int c = 0; c < 8; c++) s += sred[c][idx];
            int jg = blockIdx.x * 32 + jj;
            g_dZt[jg * 16 + b] = LRC * s * g_Gp[b * D1 + jg];
        }
    } else {
        // output = Hd @ Wo^T (split-2, 4 rows/block), 256 blocks -> 1024 rows
        __shared__ float sm[4][2][B];
        int bx2  = blockIdx.x - 128;            // 0..255
        int w    = tid >> 5;
        int lane = tid & 31;
        int r = w >> 1;
        int s = w & 1;
        int n = bx2 * 4 + r;
        const float* wrow = Wo + (size_t)n * HH + s * 512;

        float acc[B];
#pragma unroll
        for (int b = 0; b < B; b++) acc[b] = 0.f;

#pragma unroll 4
        for (int it = 0; it < 4; it++) {
            int h0 = it * 128 + lane * 4;
            float4 w4 = __ldg((const float4*)(wrow + h0));
#pragma unroll
            for (int b = 0; b < B; b++) {
                float4 h4 = *(const float4*)(g_Hd + b * HH + s * 512 + h0);
                acc[b] += dot4(w4, h4);
            }
        }
#pragma unroll
        for (int b = 0; b < B; b++) acc[b] = warp_sum(acc[b]);
        if (lane == 0) {
#pragma unroll
            for (int b = 0; b < B; b++) sm[r][s][b] = acc[b];
        }
        __syncthreads();
        if (tid < 64) {
            int rr = tid >> 4;
            int b  = tid & 15;
            int nn = bx2 * 4 + rr;
            out[b * IN + nn] = sm[rr][0][b] + sm[rr][1][b];
        }
    }
}

// ---------------- unified update: 8192 uniform blocks, 64 KB writes each ----------------
// blocks 0..4095:    W0_new[b,d1,:]           = W0[d1,:] - dZ'[b,d1] * K[b,:]   (dZ' pre-scaled)
// blocks 4096..8191: W1_new[b,i,jt*1024+1024) = W1[i,..] - LR*dH[b,i]*G[b,..]
__global__ void __launch_bounds__(256, 2)
update_kernel(const float* __restrict__ W0,
              const float* __restrict__ W1,
              float* __restrict__ out_w0,
              float* __restrict__ out_w1) {
    int tid = threadIdx.x;
    int col = tid * 4;
    if (blockIdx.x < 4096) {
        int d1 = blockIdx.x;
        float4 s0 = *(const float4*)(g_dZt + d1 * 16);
        float4 s1 = *(const float4*)(g_dZt + d1 * 16 + 4);
        float4 s2 = *(const float4*)(g_dZt + d1 * 16 + 8);
        float4 s3 = *(const float4*)(g_dZt + d1 * 16 + 12);
        float s[16] = {s0.x, s0.y, s0.z, s0.w, s1.x, s1.y, s1.z, s1.w,
                       s2.x, s2.y, s2.z, s2.w, s3.x, s3.y, s3.z, s3.w};
        float4 w4 = __ldg((const float4*)(W0 + (size_t)d1 * DKK + col));
        float* dst = out_w0 + (size_t)d1 * DKK + col;
#pragma unroll
        for (int b = 0; b < 16; b++) {
            float4 a4 = *(const float4*)(g_K + b * DKK + col);
            float4 o;
            o.x = w4.x - s[b] * a4.x;
            o.y = w4.y - s[b] * a4.y;
            o.z = w4.z - s[b] * a4.z;
            o.w = w4.w - s[b] * a4.w;
            __stcs((float4*)(dst + (size_t)b * D1 * DKK), o);
        }
    } else {
        int t  = blockIdx.x - 4096;
        int i  = t >> 2;
        int j  = (t & 3) * 1024 + col;
        float4 d0 = *(const float4*)(g_dHt + i * 16);
        float4 d1v = *(const float4*)(g_dHt + i * 16 + 4);
        float4 d2 = *(const float4*)(g_dHt + i * 16 + 8);
        float4 d3 = *(const float4*)(g_dHt + i * 16 + 12);
        float s[16] = {d0.x, d0.y, d0.z, d0.w, d1v.x, d1v.y, d1v.z, d1v.w,
                       d2.x, d2.y, d2.z, d2.w, d3.x, d3.y, d3.z, d3.w};
#pragma unroll
        for (int b = 0; b < 16; b++) s[b] *= LRC;
        float4 w4 = __ldg((const float4*)(W1 + (size_t)i * D1 + j));
        float* dst = out_w1 + (size_t)i * D1 + j;
#pragma unroll
        for (int b = 0; b < 16; b++) {
            float4 a4 = *(const float4*)(g_G + b * D1 + j);
            float4 o;
            o.x = w4.x - s[b] * a4.x;
            o.y = w4.y - s[b] * a4.y;
            o.z = w4.z - s[b] * a4.z;
            o.w = w4.w - s[b] * a4.w;
            __stcs((float4*)(dst + (size_t)b * HH * D1), o);
        }
    }
}

extern "C" void kernel_launch(void* const* d_in, const int* in_sizes, int n_in,
                              void* d_out, int out_size) {
    const float* x  = (const float*)d_in[0];
    const float* Wk = (const float*)d_in[1];
    const float* Wv = (const float*)d_in[2];
    const float* Wo = (const float*)d_in[3];
    const float* W0 = (const float*)d_in[4];
    const float* W1 = (const float*)d_in[5];

    float* out    = (float*)d_out;
    float* out_w0 = out + (size_t)B * IN;
    float* out_w1 = out_w0 + (size_t)B * D1 * DKK;

    proj_kernel  <<<128, 256>>>(x, Wk, Wv);
    zgelu_kernel <<<256, 256>>>(W0);
    hdh_kernel   <<<128, 256>>>(W1);
    dz_out_kernel<<<384, 256>>>(W1, Wo, out);
    update_kernel<<<8192, 256>>>(W0, W1, out_w0, out_w1);
}

// round 9
// speedup vs baseline: 1.1171x; 1.1171x over previous
#include <cuda_runtime.h>
#include <math.h>

#define B    16
#define IN   1024
#define HH   1024
#define DKK  1024
#define D1   4096
#define LRC  0.01f
#define NCH  64
#define CI   16

// ---------------- scratch (allocation-free) ----------------
__device__ __align__(16) float g_K  [B * DKK];          // b-major
__device__ __align__(16) float g_V  [B * HH];           // b-major
__device__ __align__(16) float g_G  [B * D1];           // b-major
__device__ __align__(16) float g_Gp [B * D1];           // b-major
__device__ __align__(16) float g_Hd [B * HH];           // b-major
__device__ __align__(16) float g_dHt[HH * B];           // i-major
__device__ __align__(16) float g_part[NCH * B * D1];    // [c][b][j], 16 MB

__device__ __forceinline__ float warp_sum(float v) {
    v += __shfl_xor_sync(0xffffffffu, v, 16);
    v += __shfl_xor_sync(0xffffffffu, v, 8);
    v += __shfl_xor_sync(0xffffffffu, v, 4);
    v += __shfl_xor_sync(0xffffffffu, v, 2);
    v += __shfl_xor_sync(0xffffffffu, v, 1);
    return v;
}
__device__ __forceinline__ float dot4(float4 a, float4 b) {
    return a.x * b.x + a.y * b.y + a.z * b.z + a.w * b.w;
}

// ---------------- proj: rows 0..1023 -> K, 1024..2047 -> V ----------------
__global__ void proj_kernel(const float* __restrict__ X,
                            const float* __restrict__ Wk,
                            const float* __restrict__ Wv) {
    __shared__ float sm[4][2][64];
    int w = threadIdx.x >> 5, lane = threadIdx.x & 31;
    int rgl = w >> 1, half = w & 1;
    int rg = blockIdx.x * 4 + rgl;            // 0..511
    const float* Wb = (rg >> 8) ? Wv : Wk;
    int row0 = (rg * 4) & 1023;
    int ibase = half * 512;
    const float* wp = Wb + (size_t)row0 * IN + ibase;
    const float* xp = X + ibase;

    float acc[4][16];
#pragma unroll
    for (int r = 0; r < 4; r++)
#pragma unroll
        for (int b = 0; b < 16; b++) acc[r][b] = 0.f;

#pragma unroll
    for (int it = 0; it < 4; it++) {
        int i = it * 128 + lane * 4;
        float4 wv[4];
#pragma unroll
        for (int r = 0; r < 4; r++) wv[r] = __ldg((const float4*)(wp + r * IN + i));
#pragma unroll
        for (int b = 0; b < 16; b++) {
            float4 x4 = __ldg((const float4*)(xp + b * IN + i));
#pragma unroll
            for (int r = 0; r < 4; r++) acc[r][b] += dot4(wv[r], x4);
        }
    }
#pragma unroll
    for (int r = 0; r < 4; r++)
#pragma unroll
        for (int b = 0; b < 16; b++) acc[r][b] = warp_sum(acc[r][b]);
    if (lane == 0) {
#pragma unroll
        for (int r = 0; r < 4; r++)
#pragma unroll
            for (int b = 0; b < 16; b++) sm[rgl][half][r * 16 + b] = acc[r][b];
    }
    __syncthreads();
    {
        int t = threadIdx.x;
        int rg2 = t >> 6, r = (t >> 4) & 3, b = t & 15;
        float v = sm[rg2][0][r * 16 + b] + sm[rg2][1][r * 16 + b];
        int row = (blockIdx.x * 4 + rg2) * 4 + r;
        float* o = (row >> 10) ? g_V : g_K;
        o[b * 1024 + (row & 1023)] = v;
    }
}

// ---------------- zgelu: Z = K @ W0^T ; G, Gp ----------------
__global__ void zgelu_kernel(const float* __restrict__ W0) {
    __shared__ float sm[4][2][64];
    int w = threadIdx.x >> 5, lane = threadIdx.x & 31;
    int rgl = w >> 1, half = w & 1;
    int rg = blockIdx.x * 4 + rgl;            // 0..1023
    int j0 = rg * 4;
    int ibase = half * 512;
    const float* wp = W0 + (size_t)j0 * DKK + ibase;

    float acc[4][16];
#pragma unroll
    for (int r = 0; r < 4; r++)
#pragma unroll
        for (int b = 0; b < 16; b++) acc[r][b] = 0.f;

#pragma unroll
    for (int it = 0; it < 4; it++) {
        int i = it * 128 + lane * 4;
        float4 wv[4];
#pragma unroll
        for (int r = 0; r < 4; r++) wv[r] = __ldg((const float4*)(wp + r * DKK + i));
#pragma unroll
        for (int b = 0; b < 16; b++) {
            float4 k4 = *(const float4*)(g_K + b * DKK + ibase + i);
#pragma unroll
            for (int r = 0; r < 4; r++) acc[r][b] += dot4(wv[r], k4);
        }
    }
#pragma unroll
    for (int r = 0; r < 4; r++)
#pragma unroll
        for (int b = 0; b < 16; b++) acc[r][b] = warp_sum(acc[r][b]);
    if (lane == 0) {
#pragma unroll
        for (int r = 0; r < 4; r++)
#pragma unroll
            for (int b = 0; b < 16; b++) sm[rgl][half][r * 16 + b] = acc[r][b];
    }
    __syncthreads();
    {
        int t = threadIdx.x;
        int rg2 = t >> 6, r = (t >> 4) & 3, b = t & 15;
        float z = sm[rg2][0][r * 16 + b] + sm[rg2][1][r * 16 + b];
        int j = (blockIdx.x * 4 + rg2) * 4 + r;
        float c  = 0.5f * (1.f + erff(z * 0.70710678118654752f));
        float g  = z * c;
        float gp = c + z * 0.39894228040143268f * expf(-0.5f * z * z);
        g_G [b * D1 + j] = g;
        g_Gp[b * D1 + j] = gp;
    }
}

// ---------------- hdh: Hd = G @ W1^T ; dH ----------------
__global__ void hdh_kernel(const float* __restrict__ W1) {
    __shared__ float sm[2][4][64];
    int w = threadIdx.x >> 5, lane = threadIdx.x & 31;
    int rgl = w >> 2, s = w & 3;
    int rg = blockIdx.x * 2 + rgl;            // 0..255
    int i0 = rg * 4;
    int jbase = s * 1024;
    const float* wp = W1 + (size_t)i0 * D1 + jbase;

    float acc[4][16];
#pragma unroll
    for (int r = 0; r < 4; r++)
#pragma unroll
        for (int b = 0; b < 16; b++) acc[r][b] = 0.f;

#pragma unroll
    for (int it = 0; it < 8; it++) {
        int j = it * 128 + lane * 4;
        float4 wv[4];
#pragma unroll
        for (int r = 0; r < 4; r++) wv[r] = __ldg((const float4*)(wp + r * D1 + j));
#pragma unroll
        for (int b = 0; b < 16; b++) {
            float4 g4 = *(const float4*)(g_G + b * D1 + jbase + j);
#pragma unroll
            for (int r = 0; r < 4; r++) acc[r][b] += dot4(wv[r], g4);
        }
    }
#pragma unroll
    for (int r = 0; r < 4; r++)
#pragma unroll
        for (int b = 0; b < 16; b++) acc[r][b] = warp_sum(acc[r][b]);
    if (lane == 0) {
#pragma unroll
        for (int r = 0; r < 4; r++)
#pragma unroll
            for (int b = 0; b < 16; b++) sm[rgl][s][r * 16 + b] = acc[r][b];
    }
    __syncthreads();
    if (threadIdx.x < 128) {
        int t = threadIdx.x;
        int rg2 = t >> 6, r = (t >> 4) & 3, b = t & 15;
        float h = sm[rg2][0][r * 16 + b] + sm[rg2][1][r * 16 + b]
                + sm[rg2][2][r * 16 + b] + sm[rg2][3][r * 16 + b];
        int i = (blockIdx.x * 2 + rg2) * 4 + r;
        g_Hd [b * HH + i] = h;
        g_dHt[i * B + b]  = (h - g_V[b * HH + i]) * (1.0f / (float)HH);
    }
}

// ---------------- MEGA: W1 update + dG partials (blocks 0..255) | output GEMV (256..511) ----------------
__global__ void __launch_bounds__(256, 2)
fused_w1_out_kernel(const float* __restrict__ W1,
                    const float* __restrict__ Wo,
                    float* __restrict__ out_w1,
                    float* __restrict__ out) {
    int tid = threadIdx.x;
    if (blockIdx.x < 256) {
        __shared__ float sdh[CI * B];
        int c  = blockIdx.x >> 2;           // 0..63
        int jt = blockIdx.x & 3;
        int i0 = c * CI;
        int j  = jt * 1024 + tid * 4;

        sdh[tid] = g_dHt[i0 * B + tid];     // 16 rows x 16 b
        __syncthreads();

#pragma unroll
        for (int half = 0; half < 2; half++) {
            float4 gg[8], acc[8];
#pragma unroll
            for (int bb = 0; bb < 8; bb++) {
                gg[bb]  = *(const float4*)(g_G + (half * 8 + bb) * D1 + j);
                acc[bb] = make_float4(0.f, 0.f, 0.f, 0.f);
            }
#pragma unroll 4
            for (int r = 0; r < CI; r++) {
                int i = i0 + r;
                float4 w4 = __ldg((const float4*)(W1 + (size_t)i * D1 + j));
                float* dst = out_w1 + (size_t)i * D1 + j;
#pragma unroll
                for (int bb = 0; bb < 8; bb++) {
                    int b = half * 8 + bb;
                    float dh = sdh[r * B + b];
                    acc[bb].x += dh * w4.x;
                    acc[bb].y += dh * w4.y;
                    acc[bb].z += dh * w4.z;
                    acc[bb].w += dh * w4.w;
                    float t = LRC * dh;
                    float4 o;
                    o.x = w4.x - t * gg[bb].x;
                    o.y = w4.y - t * gg[bb].y;
                    o.z = w4.z - t * gg[bb].z;
                    o.w = w4.w - t * gg[bb].w;
                    __stcs((float4*)(dst + (size_t)b * HH * D1), o);
                }
            }
#pragma unroll
            for (int bb = 0; bb < 8; bb++)
                *(float4*)(g_part + ((size_t)c * B + half * 8 + bb) * D1 + j) = acc[bb];
        }
    } else {
        // output = Hd @ Wo^T (split-2, 4 rows/block)
        __shared__ float sm[4][2][B];
        int bx2  = blockIdx.x - 256;
        int w    = tid >> 5;
        int lane = tid & 31;
        int r = w >> 1;
        int s = w & 1;
        int n = bx2 * 4 + r;
        const float* wrow = Wo + (size_t)n * HH + s * 512;

        float acc[B];
#pragma unroll
        for (int b = 0; b < B; b++) acc[b] = 0.f;

#pragma unroll 4
        for (int it = 0; it < 4; it++) {
            int h0 = it * 128 + lane * 4;
            float4 w4 = __ldg((const float4*)(wrow + h0));
#pragma unroll
            for (int b = 0; b < B; b++) {
                float4 h4 = *(const float4*)(g_Hd + b * HH + s * 512 + h0);
                acc[b] += dot4(w4, h4);
            }
        }
#pragma unroll
        for (int b = 0; b < B; b++) acc[b] = warp_sum(acc[b]);
        if (lane == 0) {
#pragma unroll
            for (int b = 0; b < B; b++) sm[r][s][b] = acc[b];
        }
        __syncthreads();
        if (tid < 64) {
            int rr = tid >> 4;
            int b  = tid & 15;
            int nn = bx2 * 4 + rr;
            out[b * IN + nn] = sm[rr][0][b] + sm[rr][1][b];
        }
    }
}

// ---------------- fused: dZ reduce + W0 update. 256 blocks x 256 thr, 16 d1-rows each ----------------
__global__ void __launch_bounds__(256, 2)
fused_w0_kernel(const float* __restrict__ W0,
                float* __restrict__ out_w0) {
    __shared__ float sdz[256];                 // [b][r]
    int tid  = threadIdx.x;
    int d1_0 = blockIdx.x * 16;

    {
        int b = tid >> 4, d = tid & 15;
        const float* pp = g_part + (size_t)b * D1 + d1_0 + d;
        float s = 0.f;
#pragma unroll 16
        for (int c = 0; c < NCH; c++)
            s += pp[(size_t)c * (B * D1)];
        sdz[b * 16 + d] = LRC * s * g_Gp[b * D1 + d1_0 + d];
    }
    __syncthreads();

    int col = tid * 4;
    float4 kk[16];
#pragma unroll
    for (int b = 0; b < 16; b++) kk[b] = *(const float4*)(g_K + b * DKK + col);

#pragma unroll 2
    for (int r = 0; r < 16; r++) {
        int d1 = d1_0 + r;
        float4 w4 = __ldg((const float4*)(W0 + (size_t)d1 * DKK + col));
#pragma unroll
        for (int b = 0; b < 16; b++) {
            float s = sdz[b * 16 + r];
            float4 o;
            o.x = w4.x - s * kk[b].x;
            o.y = w4.y - s * kk[b].y;
            o.z = w4.z - s * kk[b].z;
            o.w = w4.w - s * kk[b].w;
            __stcs((float4*)(out_w0 + ((size_t)b * D1 + d1) * DKK + col), o);
        }
    }
}

extern "C" void kernel_launch(void* const* d_in, const int* in_sizes, int n_in,
                              void* d_out, int out_size) {
    const float* x  = (const float*)d_in[0];
    const float* Wk = (const float*)d_in[1];
    const float* Wv = (const float*)d_in[2];
    const float* Wo = (const float*)d_in[3];
    const float* W0 = (const float*)d_in[4];
    const float* W1 = (const float*)d_in[5];

    float* out    = (float*)d_out;
    float* out_w0 = out + (size_t)B * IN;
    float* out_w1 = out_w0 + (size_t)B * D1 * DKK;

    proj_kernel        <<<128, 256>>>(x, Wk, Wv);
    zgelu_kernel       <<<256, 256>>>(W0);
    hdh_kernel         <<<128, 256>>>(W1);
    fused_w1_out_kernel<<<512, 256>>>(W1, Wo, out_w1, out);
    fused_w0_kernel    <<<256, 256>>>(W0, out_w0);
}

// round 10
// speedup vs baseline: 1.1214x; 1.0038x over previous
#include <cuda_runtime.h>
#include <math.h>

#define B    16
#define IN   1024
#define HH   1024
#define DKK  1024
#define D1   4096
#define LRC  0.01f
#define NCH  64
#define CI   16

// ---------------- scratch (allocation-free) ----------------
__device__ __align__(16) float g_K  [B * DKK];          // b-major
__device__ __align__(16) float g_V  [B * HH];           // b-major
__device__ __align__(16) float g_G  [B * D1];           // b-major
__device__ __align__(16) float g_Gp [B * D1];           // b-major
__device__ __align__(16) float g_Hd [B * HH];           // b-major
__device__ __align__(16) float g_dHt[HH * B];           // i-major
__device__ __align__(16) float g_part[NCH * B * D1];    // [c][b][j], 16 MB

__device__ __forceinline__ float warp_sum(float v) {
    v += __shfl_xor_sync(0xffffffffu, v, 16);
    v += __shfl_xor_sync(0xffffffffu, v, 8);
    v += __shfl_xor_sync(0xffffffffu, v, 4);
    v += __shfl_xor_sync(0xffffffffu, v, 2);
    v += __shfl_xor_sync(0xffffffffu, v, 1);
    return v;
}
__device__ __forceinline__ float dot4(float4 a, float4 b) {
    return a.x * b.x + a.y * b.y + a.z * b.z + a.w * b.w;
}

// shared GEMV body: 4 row-groups x 2 halves, writes result rows via epilogue
// (inlined manually in each kernel below to keep role dispatch simple)

// ---------------- proj: K only (64 blocks) ----------------
__global__ void proj_kernel(const float* __restrict__ X,
                            const float* __restrict__ Wk) {
    __shared__ float sm[4][2][64];
    int w = threadIdx.x >> 5, lane = threadIdx.x & 31;
    int rgl = w >> 1, half = w & 1;
    int rg = blockIdx.x * 4 + rgl;            // 0..255
    int row0 = rg * 4;
    int ibase = half * 512;
    const float* wp = Wk + (size_t)row0 * IN + ibase;
    const float* xp = X + ibase;

    float acc[4][16];
#pragma unroll
    for (int r = 0; r < 4; r++)
#pragma unroll
        for (int b = 0; b < 16; b++) acc[r][b] = 0.f;

#pragma unroll
    for (int it = 0; it < 4; it++) {
        int i = it * 128 + lane * 4;
        float4 wv[4];
#pragma unroll
        for (int r = 0; r < 4; r++) wv[r] = __ldg((const float4*)(wp + r * IN + i));
#pragma unroll
        for (int b = 0; b < 16; b++) {
            float4 x4 = __ldg((const float4*)(xp + b * IN + i));
#pragma unroll
            for (int r = 0; r < 4; r++) acc[r][b] += dot4(wv[r], x4);
        }
    }
#pragma unroll
    for (int r = 0; r < 4; r++)
#pragma unroll
        for (int b = 0; b < 16; b++) acc[r][b] = warp_sum(acc[r][b]);
    if (lane == 0) {
#pragma unroll
        for (int r = 0; r < 4; r++)
#pragma unroll
            for (int b = 0; b < 16; b++) sm[rgl][half][r * 16 + b] = acc[r][b];
    }
    __syncthreads();
    {
        int t = threadIdx.x;
        int rg2 = t >> 6, r = (t >> 4) & 3, b = t & 15;
        float v = sm[rg2][0][r * 16 + b] + sm[rg2][1][r * 16 + b];
        int row = (blockIdx.x * 4 + rg2) * 4 + r;
        g_K[b * 1024 + row] = v;
    }
}

// ---------------- zgelu (blocks 0..255) | V projection (blocks 256..319) ----------------
__global__ void zgelu_v_kernel(const float* __restrict__ W0,
                               const float* __restrict__ X,
                               const float* __restrict__ Wv) {
    __shared__ float sm[4][2][64];
    int w = threadIdx.x >> 5, lane = threadIdx.x & 31;
    int rgl = w >> 1, half = w & 1;
    int ibase = half * 512;

    if (blockIdx.x < 256) {
        int rg = blockIdx.x * 4 + rgl;            // 0..1023
        int j0 = rg * 4;
        const float* wp = W0 + (size_t)j0 * DKK + ibase;

        float acc[4][16];
#pragma unroll
        for (int r = 0; r < 4; r++)
#pragma unroll
            for (int b = 0; b < 16; b++) acc[r][b] = 0.f;

#pragma unroll
        for (int it = 0; it < 4; it++) {
            int i = it * 128 + lane * 4;
            float4 wv[4];
#pragma unroll
            for (int r = 0; r < 4; r++) wv[r] = __ldg((const float4*)(wp + r * DKK + i));
#pragma unroll
            for (int b = 0; b < 16; b++) {
                float4 k4 = *(const float4*)(g_K + b * DKK + ibase + i);
#pragma unroll
                for (int r = 0; r < 4; r++) acc[r][b] += dot4(wv[r], k4);
            }
        }
#pragma unroll
        for (int r = 0; r < 4; r++)
#pragma unroll
            for (int b = 0; b < 16; b++) acc[r][b] = warp_sum(acc[r][b]);
        if (lane == 0) {
#pragma unroll
            for (int r = 0; r < 4; r++)
#pragma unroll
                for (int b = 0; b < 16; b++) sm[rgl][half][r * 16 + b] = acc[r][b];
        }
        __syncthreads();
        {
            int t = threadIdx.x;
            int rg2 = t >> 6, r = (t >> 4) & 3, b = t & 15;
            float z = sm[rg2][0][r * 16 + b] + sm[rg2][1][r * 16 + b];
            int j = (blockIdx.x * 4 + rg2) * 4 + r;
            float c  = 0.5f * (1.f + erff(z * 0.70710678118654752f));
            float g  = z * c;
            float gp = c + z * 0.39894228040143268f * expf(-0.5f * z * z);
            g_G [b * D1 + j] = g;
            g_Gp[b * D1 + j] = gp;
        }
    } else {
        // V = X @ Wv^T (64 blocks x 16 rows)
        int bx2 = blockIdx.x - 256;               // 0..63
        int rg = bx2 * 4 + rgl;                   // 0..255
        int row0 = rg * 4;
        const float* wp = Wv + (size_t)row0 * IN + ibase;
        const float* xp = X + ibase;

        float acc[4][16];
#pragma unroll
        for (int r = 0; r < 4; r++)
#pragma unroll
            for (int b = 0; b < 16; b++) acc[r][b] = 0.f;

#pragma unroll
        for (int it = 0; it < 4; it++) {
            int i = it * 128 + lane * 4;
            float4 wv[4];
#pragma unroll
            for (int r = 0; r < 4; r++) wv[r] = __ldg((const float4*)(wp + r * IN + i));
#pragma unroll
            for (int b = 0; b < 16; b++) {
                float4 x4 = __ldg((const float4*)(xp + b * IN + i));
#pragma unroll
                for (int r = 0; r < 4; r++) acc[r][b] += dot4(wv[r], x4);
            }
        }
#pragma unroll
        for (int r = 0; r < 4; r++)
#pragma unroll
            for (int b = 0; b < 16; b++) acc[r][b] = warp_sum(acc[r][b]);
        if (lane == 0) {
#pragma unroll
            for (int r = 0; r < 4; r++)
#pragma unroll
                for (int b = 0; b < 16; b++) sm[rgl][half][r * 16 + b] = acc[r][b];
        }
        __syncthreads();
        {
            int t = threadIdx.x;
            int rg2 = t >> 6, r = (t >> 4) & 3, b = t & 15;
            float v = sm[rg2][0][r * 16 + b] + sm[rg2][1][r * 16 + b];
            int row = (bx2 * 4 + rg2) * 4 + r;
            g_V[b * 1024 + row] = v;
        }
    }
}

// ---------------- hdh: Hd = G @ W1^T ; dH ----------------
__global__ void hdh_kernel(const float* __restrict__ W1) {
    __shared__ float sm[2][4][64];
    int w = threadIdx.x >> 5, lane = threadIdx.x & 31;
    int rgl = w >> 2, s = w & 3;
    int rg = blockIdx.x * 2 + rgl;            // 0..255
    int i0 = rg * 4;
    int jbase = s * 1024;
    const float* wp = W1 + (size_t)i0 * D1 + jbase;

    float acc[4][16];
#pragma unroll
    for (int r = 0; r < 4; r++)
#pragma unroll
        for (int b = 0; b < 16; b++) acc[r][b] = 0.f;

#pragma unroll
    for (int it = 0; it < 8; it++) {
        int j = it * 128 + lane * 4;
        float4 wv[4];
#pragma unroll
        for (int r = 0; r < 4; r++) wv[r] = __ldg((const float4*)(wp + r * D1 + j));
#pragma unroll
        for (int b = 0; b < 16; b++) {
            float4 g4 = *(const float4*)(g_G + b * D1 + jbase + j);
#pragma unroll
            for (int r = 0; r < 4; r++) acc[r][b] += dot4(wv[r], g4);
        }
    }
#pragma unroll
    for (int r = 0; r < 4; r++)
#pragma unroll
        for (int b = 0; b < 16; b++) acc[r][b] = warp_sum(acc[r][b]);
    if (lane == 0) {
#pragma unroll
        for (int r = 0; r < 4; r++)
#pragma unroll
            for (int b = 0; b < 16; b++) sm[rgl][s][r * 16 + b] = acc[r][b];
    }
    __syncthreads();
    if (threadIdx.x < 128) {
        int t = threadIdx.x;
        int rg2 = t >> 6, r = (t >> 4) & 3, b = t & 15;
        float h = sm[rg2][0][r * 16 + b] + sm[rg2][1][r * 16 + b]
                + sm[rg2][2][r * 16 + b] + sm[rg2][3][r * 16 + b];
        int i = (blockIdx.x * 2 + rg2) * 4 + r;
        g_Hd [b * HH + i] = h;
        g_dHt[i * B + b]  = (h - g_V[b * HH + i]) * (1.0f / (float)HH);
    }
}

// ---------------- MEGA: W1 update + dG partials (blocks 0..255) | output GEMV (256..511) ----------------
__global__ void fused_w1_out_kernel(const float* __restrict__ W1,
                                    const float* __restrict__ Wo,
                                    float* __restrict__ out_w1,
                                    float* __restrict__ out) {
    int tid = threadIdx.x;
    if (blockIdx.x < 256) {
        __shared__ float sdh[CI * B];
        int c  = blockIdx.x >> 2;           // 0..63
        int jt = blockIdx.x & 3;
        int i0 = c * CI;
        int j  = jt * 1024 + tid * 4;

        sdh[tid] = g_dHt[i0 * B + tid];     // 16 rows x 16 b
        __syncthreads();

#pragma unroll
        for (int half = 0; half < 2; half++) {
            float4 gg[8], acc[8];
#pragma unroll
            for (int bb = 0; bb < 8; bb++) {
                gg[bb]  = *(const float4*)(g_G + (half * 8 + bb) * D1 + j);
                acc[bb] = make_float4(0.f, 0.f, 0.f, 0.f);
            }
#pragma unroll 4
            for (int r = 0; r < CI; r++) {
                int i = i0 + r;
                float4 w4 = __ldg((const float4*)(W1 + (size_t)i * D1 + j));
                float* dst = out_w1 + (size_t)i * D1 + j;
#pragma unroll
                for (int bb = 0; bb < 8; bb++) {
                    int b = half * 8 + bb;
                    float dh = sdh[r * B + b];
                    acc[bb].x += dh * w4.x;
                    acc[bb].y += dh * w4.y;
                    acc[bb].z += dh * w4.z;
                    acc[bb].w += dh * w4.w;
                    float t = LRC * dh;
                    float4 o;
                    o.x = w4.x - t * gg[bb].x;
                    o.y = w4.y - t * gg[bb].y;
                    o.z = w4.z - t * gg[bb].z;
                    o.w = w4.w - t * gg[bb].w;
                    __stcs((float4*)(dst + (size_t)b * HH * D1), o);
                }
            }
#pragma unroll
            for (int bb = 0; bb < 8; bb++)
                *(float4*)(g_part + ((size_t)c * B + half * 8 + bb) * D1 + j) = acc[bb];
        }
    } else {
        // output = Hd @ Wo^T (split-2, 4 rows/block)
        __shared__ float sm[4][2][B];
        int bx2  = blockIdx.x - 256;
        int w    = tid >> 5;
        int lane = tid & 31;
        int r = w >> 1;
        int s = w & 1;
        int n = bx2 * 4 + r;
        const float* wrow = Wo + (size_t)n * HH + s * 512;

        float acc[B];
#pragma unroll
        for (int b = 0; b < B; b++) acc[b] = 0.f;

#pragma unroll 4
        for (int it = 0; it < 4; it++) {
            int h0 = it * 128 + lane * 4;
            float4 w4 = __ldg((const float4*)(wrow + h0));
#pragma unroll
            for (int b = 0; b < B; b++) {
                float4 h4 = *(const float4*)(g_Hd + b * HH + s * 512 + h0);
                acc[b] += dot4(w4, h4);
            }
        }
#pragma unroll
        for (int b = 0; b < B; b++) acc[b] = warp_sum(acc[b]);
        if (lane == 0) {
#pragma unroll
            for (int b = 0; b < B; b++) sm[r][s][b] = acc[b];
        }
        __syncthreads();
        if (tid < 64) {
            int rr = tid >> 4;
            int b  = tid & 15;
            int nn = bx2 * 4 + rr;
            out[b * IN + nn] = sm[rr][0][b] + sm[rr][1][b];
        }
    }
}

// ---------------- fused: dZ reduce + W0 update. 256 blocks x 256 thr, 16 d1-rows each ----------------
__global__ void fused_w0_kernel(const float* __restrict__ W0,
                                float* __restrict__ out_w0) {
    __shared__ float sdz[256];                 // [b][r]
    int tid  = threadIdx.x;
    int d1_0 = blockIdx.x * 16;

    {
        int b = tid >> 4, d = tid & 15;
        const float* pp = g_part + (size_t)b * D1 + d1_0 + d;
        float s = 0.f;
#pragma unroll 16
        for (int c = 0; c < NCH; c++)
            s += pp[(size_t)c * (B * D1)];
        sdz[b * 16 + d] = LRC * s * g_Gp[b * D1 + d1_0 + d];
    }
    __syncthreads();

    int col = tid * 4;
    float4 kk[16];
#pragma unroll
    for (int b = 0; b < 16; b++) kk[b] = *(const float4*)(g_K + b * DKK + col);

#pragma unroll 2
    for (int r = 0; r < 16; r++) {
        int d1 = d1_0 + r;
        float4 w4 = __ldg((const float4*)(W0 + (size_t)d1 * DKK + col));
#pragma unroll
        for (int b = 0; b < 16; b++) {
            float s = sdz[b * 16 + r];
            float4 o;
            o.x = w4.x - s * kk[b].x;
            o.y = w4.y - s * kk[b].y;
            o.z = w4.z - s * kk[b].z;
            o.w = w4.w - s * kk[b].w;
            __stcs((float4*)(out_w0 + ((size_t)b * D1 + d1) * DKK + col), o);
        }
    }
}

extern "C" void kernel_launch(void* const* d_in, const int* in_sizes, int n_in,
                              void* d_out, int out_size) {
    const float* x  = (const float*)d_in[0];
    const float* Wk = (const float*)d_in[1];
    const float* Wv = (const float*)d_in[2];
    const float* Wo = (const float*)d_in[3];
    const float* W0 = (const float*)d_in[4];
    const float* W1 = (const float*)d_in[5];

    float* out    = (float*)d_out;
    float* out_w0 = out + (size_t)B * IN;
    float* out_w1 = out_w0 + (size_t)B * D1 * DKK;

    proj_kernel        <<<64,  256>>>(x, Wk);            // K only
    zgelu_v_kernel     <<<320, 256>>>(W0, x, Wv);        // zgelu + V rides along
    hdh_kernel         <<<128, 256>>>(W1);
    fused_w1_out_kernel<<<512, 256>>>(W1, Wo, out_w1, out);
    fused_w0_kernel    <<<256, 256>>>(W0, out_w0);
}

// round 11
// speedup vs baseline: 1.1224x; 1.0009x over previous
#include <cuda_runtime.h>
#include <math.h>

#define B    16
#define IN   1024
#define HH   1024
#define DKK  1024
#define D1   4096
#define LRC  0.01f
#define NCH  64
#define CI   16

// ---------------- scratch (allocation-free) ----------------
__device__ __align__(16) float g_K  [B * DKK];          // b-major
__device__ __align__(16) float g_V  [B * HH];           // b-major
__device__ __align__(16) float g_G  [B * D1];           // b-major
__device__ __align__(16) float g_Gp [B * D1];           // b-major
__device__ __align__(16) float g_Hd [B * HH];           // b-major
__device__ __align__(16) float g_dHt[HH * B];           // i-major
__device__ __align__(16) float g_part[NCH * B * D1];    // [c][b][j], 16 MB

__device__ __forceinline__ float warp_sum(float v) {
    v += __shfl_xor_sync(0xffffffffu, v, 16);
    v += __shfl_xor_sync(0xffffffffu, v, 8);
    v += __shfl_xor_sync(0xffffffffu, v, 4);
    v += __shfl_xor_sync(0xffffffffu, v, 2);
    v += __shfl_xor_sync(0xffffffffu, v, 1);
    return v;
}
__device__ __forceinline__ float dot4(float4 a, float4 b) {
    return a.x * b.x + a.y * b.y + a.z * b.z + a.w * b.w;
}

// ---------------- proj: rows 0..1023 -> K, 1024..2047 -> V (256 blocks, 2 rows/warp) ----------------
__global__ void proj_kernel(const float* __restrict__ X,
                            const float* __restrict__ Wk,
                            const float* __restrict__ Wv) {
    __shared__ float sm[4][2][32];
    int w = threadIdx.x >> 5, lane = threadIdx.x & 31;
    int rgl = w >> 1, half = w & 1;
    int rg = blockIdx.x * 4 + rgl;            // 0..1023, each = 2 rows
    const float* Wb = (rg >> 9) ? Wv : Wk;
    int row0 = (rg * 2) & 1023;
    int ibase = half * 512;
    const float* wp = Wb + (size_t)row0 * IN + ibase;
    const float* xp = X + ibase;

    float acc[2][16];
#pragma unroll
    for (int r = 0; r < 2; r++)
#pragma unroll
        for (int b = 0; b < 16; b++) acc[r][b] = 0.f;

#pragma unroll
    for (int it = 0; it < 4; it++) {
        int i = it * 128 + lane * 4;
        float4 wv[2];
#pragma unroll
        for (int r = 0; r < 2; r++) wv[r] = __ldg((const float4*)(wp + r * IN + i));
#pragma unroll
        for (int b = 0; b < 16; b++) {
            float4 x4 = __ldg((const float4*)(xp + b * IN + i));
#pragma unroll
            for (int r = 0; r < 2; r++) acc[r][b] += dot4(wv[r], x4);
        }
    }
#pragma unroll
    for (int r = 0; r < 2; r++)
#pragma unroll
        for (int b = 0; b < 16; b++) acc[r][b] = warp_sum(acc[r][b]);
    if (lane == 0) {
#pragma unroll
        for (int r = 0; r < 2; r++)
#pragma unroll
            for (int b = 0; b < 16; b++) sm[rgl][half][r * 16 + b] = acc[r][b];
    }
    __syncthreads();
    if (threadIdx.x < 128) {
        int t = threadIdx.x;
        int rg2 = t >> 5, r = (t >> 4) & 1, b = t & 15;
        float v = sm[rg2][0][r * 16 + b] + sm[rg2][1][r * 16 + b];
        int row = (blockIdx.x * 4 + rg2) * 2 + r;
        float* o = (row >> 10) ? g_V : g_K;
        o[b * 1024 + (row & 1023)] = v;
    }
}

// ---------------- zgelu: Z = K @ W0^T ; G, Gp (512 blocks, 2 rows/warp) ----------------
__global__ void zgelu_kernel(const float* __restrict__ W0) {
    __shared__ float sm[4][2][32];
    int w = threadIdx.x >> 5, lane = threadIdx.x & 31;
    int rgl = w >> 1, half = w & 1;
    int rg = blockIdx.x * 4 + rgl;            // 0..2047, each = 2 rows
    int j0 = rg * 2;
    int ibase = half * 512;
    const float* wp = W0 + (size_t)j0 * DKK + ibase;

    float acc[2][16];
#pragma unroll
    for (int r = 0; r < 2; r++)
#pragma unroll
        for (int b = 0; b < 16; b++) acc[r][b] = 0.f;

#pragma unroll
    for (int it = 0; it < 4; it++) {
        int i = it * 128 + lane * 4;
        float4 wv[2];
#pragma unroll
        for (int r = 0; r < 2; r++) wv[r] = __ldg((const float4*)(wp + r * DKK + i));
#pragma unroll
        for (int b = 0; b < 16; b++) {
            float4 k4 = *(const float4*)(g_K + b * DKK + ibase + i);
#pragma unroll
            for (int r = 0; r < 2; r++) acc[r][b] += dot4(wv[r], k4);
        }
    }
#pragma unroll
    for (int r = 0; r < 2; r++)
#pragma unroll
        for (int b = 0; b < 16; b++) acc[r][b] = warp_sum(acc[r][b]);
    if (lane == 0) {
#pragma unroll
        for (int r = 0; r < 2; r++)
#pragma unroll
            for (int b = 0; b < 16; b++) sm[rgl][half][r * 16 + b] = acc[r][b];
    }
    __syncthreads();
    if (threadIdx.x < 128) {
        int t = threadIdx.x;
        int rg2 = t >> 5, r = (t >> 4) & 1, b = t & 15;
        float z = sm[rg2][0][r * 16 + b] + sm[rg2][1][r * 16 + b];
        int j = (blockIdx.x * 4 + rg2) * 2 + r;
        float c  = 0.5f * (1.f + erff(z * 0.70710678118654752f));
        float g  = z * c;
        float gp = c + z * 0.39894228040143268f * expf(-0.5f * z * z);
        g_G [b * D1 + j] = g;
        g_Gp[b * D1 + j] = gp;
    }
}

// ---------------- hdh: Hd = G @ W1^T ; dH (256 blocks, 2 rows/warp, split-4) ----------------
__global__ void hdh_kernel(const float* __restrict__ W1) {
    __shared__ float sm[2][4][32];
    int w = threadIdx.x >> 5, lane = threadIdx.x & 31;
    int rgl = w >> 2, s = w & 3;
    int rg = blockIdx.x * 2 + rgl;            // 0..511, each = 2 rows
    int i0 = rg * 2;
    int jbase = s * 1024;
    const float* wp = W1 + (size_t)i0 * D1 + jbase;

    float acc[2][16];
#pragma unroll
    for (int r = 0; r < 2; r++)
#pragma unroll
        for (int b = 0; b < 16; b++) acc[r][b] = 0.f;

#pragma unroll
    for (int it = 0; it < 8; it++) {
        int j = it * 128 + lane * 4;
        float4 wv[2];
#pragma unroll
        for (int r = 0; r < 2; r++) wv[r] = __ldg((const float4*)(wp + r * D1 + j));
#pragma unroll
        for (int b = 0; b < 16; b++) {
            float4 g4 = *(const float4*)(g_G + b * D1 + jbase + j);
#pragma unroll
            for (int r = 0; r < 2; r++) acc[r][b] += dot4(wv[r], g4);
        }
    }
#pragma unroll
    for (int r = 0; r < 2; r++)
#pragma unroll
        for (int b = 0; b < 16; b++) acc[r][b] = warp_sum(acc[r][b]);
    if (lane == 0) {
#pragma unroll
        for (int r = 0; r < 2; r++)
#pragma unroll
            for (int b = 0; b < 16; b++) sm[rgl][s][r * 16 + b] = acc[r][b];
    }
    __syncthreads();
    if (threadIdx.x < 64) {
        int t = threadIdx.x;
        int rg2 = t >> 5, r = (t >> 4) & 1, b = t & 15;
        float h = sm[rg2][0][r * 16 + b] + sm[rg2][1][r * 16 + b]
                + sm[rg2][2][r * 16 + b] + sm[rg2][3][r * 16 + b];
        int i = (blockIdx.x * 2 + rg2) * 2 + r;
        g_Hd [b * HH + i] = h;
        g_dHt[i * B + b]  = (h - g_V[b * HH + i]) * (1.0f / (float)HH);
    }
}

// ---------------- MEGA: W1 update + dG partials (blocks 0..255) | output GEMV (256..511) ----------------
__global__ void fused_w1_out_kernel(const float* __restrict__ W1,
                                    const float* __restrict__ Wo,
                                    float* __restrict__ out_w1,
                                    float* __restrict__ out) {
    int tid = threadIdx.x;
    if (blockIdx.x < 256) {
        __shared__ float sdh[CI * B];
        int c  = blockIdx.x >> 2;           // 0..63
        int jt = blockIdx.x & 3;
        int i0 = c * CI;
        int j  = jt * 1024 + tid * 4;

        sdh[tid] = g_dHt[i0 * B + tid];     // 16 rows x 16 b
        __syncthreads();

#pragma unroll
        for (int half = 0; half < 2; half++) {
            float4 gg[8], acc[8];
#pragma unroll
            for (int bb = 0; bb < 8; bb++) {
                gg[bb]  = *(const float4*)(g_G + (half * 8 + bb) * D1 + j);
                acc[bb] = make_float4(0.f, 0.f, 0.f, 0.f);
            }
#pragma unroll 4
            for (int r = 0; r < CI; r++) {
                int i = i0 + r;
                float4 w4 = __ldg((const float4*)(W1 + (size_t)i * D1 + j));
                float* dst = out_w1 + (size_t)i * D1 + j;
#pragma unroll
                for (int bb = 0; bb < 8; bb++) {
                    int b = half * 8 + bb;
                    float dh = sdh[r * B + b];
                    acc[bb].x += dh * w4.x;
                    acc[bb].y += dh * w4.y;
                    acc[bb].z += dh * w4.z;
                    acc[bb].w += dh * w4.w;
                    float t = LRC * dh;
                    float4 o;
                    o.x = w4.x - t * gg[bb].x;
                    o.y = w4.y - t * gg[bb].y;
                    o.z = w4.z - t * gg[bb].z;
                    o.w = w4.w - t * gg[bb].w;
                    __stcs((float4*)(dst + (size_t)b * HH * D1), o);
                }
            }
#pragma unroll
            for (int bb = 0; bb < 8; bb++)
                *(float4*)(g_part + ((size_t)c * B + half * 8 + bb) * D1 + j) = acc[bb];
        }
    } else {
        // output = Hd @ Wo^T (split-2, 4 rows/block)
        __shared__ float sm[4][2][B];
        int bx2  = blockIdx.x - 256;
        int w    = tid >> 5;
        int lane = tid & 31;
        int r = w >> 1;
        int s = w & 1;
        int n = bx2 * 4 + r;
        const float* wrow = Wo + (size_t)n * HH + s * 512;

        float acc[B];
#pragma unroll
        for (int b = 0; b < B; b++) acc[b] = 0.f;

#pragma unroll 4
        for (int it = 0; it < 4; it++) {
            int h0 = it * 128 + lane * 4;
            float4 w4 = __ldg((const float4*)(wrow + h0));
#pragma unroll
            for (int b = 0; b < B; b++) {
                float4 h4 = *(const float4*)(g_Hd + b * HH + s * 512 + h0);
                acc[b] += dot4(w4, h4);
            }
        }
#pragma unroll
        for (int b = 0; b < B; b++) acc[b] = warp_sum(acc[b]);
        if (lane == 0) {
#pragma unroll
            for (int b = 0; b < B; b++) sm[r][s][b] = acc[b];
        }
        __syncthreads();
        if (tid < 64) {
            int rr = tid >> 4;
            int b  = tid & 15;
            int nn = bx2 * 4 + rr;
            out[b * IN + nn] = sm[rr][0][b] + sm[rr][1][b];
        }
    }
}

// ---------------- fused: dZ reduce + W0 update. 256 blocks x 256 thr, 16 d1-rows each ----------------
__global__ void fused_w0_kernel(const float* __restrict__ W0,
                                float* __restrict__ out_w0) {
    __shared__ float sdz[256];                 // [b][r]
    int tid  = threadIdx.x;
    int d1_0 = blockIdx.x * 16;

    {
        int b = tid >> 4, d = tid & 15;
        const float* pp = g_part + (size_t)b * D1 + d1_0 + d;
        float s = 0.f;
#pragma unroll 16
        for (int c = 0; c < NCH; c++)
            s += pp[(size_t)c * (B * D1)];
        sdz[b * 16 + d] = LRC * s * g_Gp[b * D1 + d1_0 + d];
    }
    __syncthreads();

    int col = tid * 4;
    float4 kk[16];
#pragma unroll
    for (int b = 0; b < 16; b++) kk[b] = *(const float4*)(g_K + b * DKK + col);

#pragma unroll 2
    for (int r = 0; r < 16; r++) {
        int d1 = d1_0 + r;
        float4 w4 = __ldg((const float4*)(W0 + (size_t)d1 * DKK + col));
#pragma unroll
        for (int b = 0; b < 16; b++) {
            float s = sdz[b * 16 + r];
            float4 o;
            o.x = w4.x - s * kk[b].x;
            o.y = w4.y - s * kk[b].y;
            o.z = w4.z - s * kk[b].z;
            o.w = w4.w - s * kk[b].w;
            __stcs((float4*)(out_w0 + ((size_t)b * D1 + d1) * DKK + col), o);
        }
    }
}

extern "C" void kernel_launch(void* const* d_in, const int* in_sizes, int n_in,
                              void* d_out, int out_size) {
    const float* x  = (const float*)d_in[0];
    const float* Wk = (const float*)d_in[1];
    const float* Wv = (const float*)d_in[2];
    const float* Wo = (const float*)d_in[3];
    const float* W0 = (const float*)d_in[4];
    const float* W1 = (const float*)d_in[5];

    float* out    = (float*)d_out;
    float* out_w0 = out + (size_t)B * IN;
    float* out_w1 = out_w0 + (size_t)B * D1 * DKK;

    proj_kernel        <<<256, 256>>>(x, Wk, Wv);
    zgelu_kernel       <<<512, 256>>>(W0);
    hdh_kernel         <<<256, 256>>>(W1);
    fused_w1_out_kernel<<<512, 256>>>(W1, Wo, out_w1, out);
    fused_w0_kernel    <<<256, 256>>>(W0, out_w0);
}